// round 14
// baseline (speedup 1.0000x reference)
#include <cuda_runtime.h>
#include <cstdint>

#define NH 12
#define HD 64
#define HID 768
#define BSC 8
#define FULLB 240
#define LQ 32
#define LEN0 512
#define LEN1 128
#define TOTKV 672
#define MROWS (FULLB*LQ)   // 7680

// Scratch
__device__ float g_q[FULLB*NH*LQ*HD];
__device__ float g_k[FULLB*NH*LQ*HD];
__device__ float g_v[FULLB*NH*LQ*HD];
__device__ float g_wt[3*HID*HID];     // Wt[n][k] = W[k][n]

__device__ __forceinline__ void mma_tf32(float* c, uint32_t a0, uint32_t a1,
                                         uint32_t a2, uint32_t a3,
                                         uint32_t b0, uint32_t b1) {
    asm volatile(
        "mma.sync.aligned.m16n8k8.row.col.f32.tf32.tf32.f32 "
        "{%0,%1,%2,%3}, {%4,%5,%6,%7}, {%8,%9}, {%0,%1,%2,%3};"
        : "+f"(c[0]), "+f"(c[1]), "+f"(c[2]), "+f"(c[3])
        : "r"(a0), "r"(a1), "r"(a2), "r"(a3), "r"(b0), "r"(b1));
}
__device__ __forceinline__ uint32_t f2tf(float x) {
    uint32_t r;
    asm("cvt.rna.tf32.f32 %0, %1;" : "=r"(r) : "f"(x));
    return r;
}
__device__ __forceinline__ float f2tff(float x) {
    return __uint_as_float(f2tf(x));
}
__device__ __forceinline__ uint32_t smem_u32(const void* p) {
    uint32_t a;
    asm("{ .reg .u64 t; cvta.to.shared.u64 t, %1; cvt.u32.u64 %0, t; }"
        : "=r"(a) : "l"(p));
    return a;
}
#define CP_A16(dst, src) \
    asm volatile("cp.async.cg.shared.global [%0], [%1], 16;" :: "r"(dst), "l"(src) : "memory")
#define CP_COMMIT() asm volatile("cp.async.commit_group;" ::: "memory")
#define CP_WAIT(n)  asm volatile("cp.async.wait_group %0;" :: "n"(n) : "memory")

// ---------------------------------------------------------------------------
// Weight transpose: Wt[n][k] = W[k][n]
// ---------------------------------------------------------------------------
__global__ __launch_bounds__(256) void transpose_w(
    const float* __restrict__ Wq, const float* __restrict__ Wk, const float* __restrict__ Wv)
{
    const float* W = blockIdx.z == 0 ? Wq : blockIdx.z == 1 ? Wk : Wv;
    float* Wt = g_wt + (size_t)blockIdx.z * HID * HID;
    __shared__ float ts[32][33];
    int tx = threadIdx.x, ty = threadIdx.y;
    int x = blockIdx.x * 32 + tx;
    int y0 = blockIdx.y * 32;
    #pragma unroll
    for (int i = 0; i < 4; i++)
        ts[ty + 8 * i][tx] = W[(size_t)(y0 + ty + 8 * i) * HID + x];
    __syncthreads();
    int x2 = blockIdx.y * 32 + tx;
    int y2 = blockIdx.x * 32;
    #pragma unroll
    for (int i = 0; i < 4; i++)
        Wt[(size_t)(y2 + ty + 8 * i) * HID + x2] = ts[tx][ty + 8 * i];
}

// ---------------------------------------------------------------------------
// TF32 QKV GEMM, double-buffered: LDG for block k+1 overlaps MMA of block k.
// One __syncthreads per k-block. rna rounding at STS.
// ---------------------------------------------------------------------------
#define KB 32
#define SAS 36
#define SMG (128*SAS)   // floats per buffer

__global__ __launch_bounds__(256) void qkv_gemm_mma(
    const float* __restrict__ A,
    const float* __restrict__ bq, const float* __restrict__ bk, const float* __restrict__ bv)
{
    extern __shared__ float sm[];
    float* const Abuf[2] = { sm,           sm + SMG };
    float* const Bbuf[2] = { sm + 2*SMG,   sm + 3*SMG };

    const int tid = threadIdx.x;
    const int wid = tid >> 5;
    const int lane = tid & 31;
    const int g = lane >> 2;
    const int tig = lane & 3;
    const int wm = wid & 1;
    const int wn = wid >> 1;

    const int z = blockIdx.z;
    const float* bias = z == 0 ? bq : z == 1 ? bk : bv;
    float* out = z == 0 ? g_q : z == 1 ? g_k : g_v;
    const float* Wt = g_wt + (size_t)z * HID * HID;
    const int m0 = blockIdx.x * 128;
    const int n0 = blockIdx.y * 128;

    const int lrow = tid >> 3;            // 0..31 base row per it-chunk group
    const int lc4  = (tid & 7) * 4;

    float c[4][4][4];
    #pragma unroll
    for (int mt = 0; mt < 4; mt++)
        #pragma unroll
        for (int nt = 0; nt < 4; nt++)
            #pragma unroll
            for (int q = 0; q < 4; q++) c[mt][nt][q] = 0.f;

    float4 ra[4], rb[4];

    // prologue: load block 0
    #pragma unroll
    for (int it = 0; it < 4; it++) {
        int row = lrow + it * 32;
        ra[it] = *(const float4*)(A  + (size_t)(m0 + row) * HID + lc4);
        rb[it] = *(const float4*)(Wt + (size_t)(n0 + row) * HID + lc4);
    }
    #pragma unroll
    for (int it = 0; it < 4; it++) {
        int row = lrow + it * 32;
        float4 av = ra[it], bv4 = rb[it];
        av.x = f2tff(av.x); av.y = f2tff(av.y); av.z = f2tff(av.z); av.w = f2tff(av.w);
        bv4.x = f2tff(bv4.x); bv4.y = f2tff(bv4.y); bv4.z = f2tff(bv4.z); bv4.w = f2tff(bv4.w);
        *(float4*)(Abuf[0] + row * SAS + lc4) = av;
        *(float4*)(Bbuf[0] + row * SAS + lc4) = bv4;
    }
    __syncthreads();

    #pragma unroll
    for (int blk = 0; blk < HID / KB; blk++) {
        const int p = blk & 1;
        if (blk < HID / KB - 1) {
            const int k0 = (blk + 1) * KB;
            #pragma unroll
            for (int it = 0; it < 4; it++) {
                int row = lrow + it * 32;
                ra[it] = *(const float4*)(A  + (size_t)(m0 + row) * HID + k0 + lc4);
                rb[it] = *(const float4*)(Wt + (size_t)(n0 + row) * HID + k0 + lc4);
            }
        }

        const float* As = Abuf[p];
        const float* Bs = Bbuf[p];
        #pragma unroll
        for (int ks = 0; ks < 4; ks++) {
            const int kb = ks * 8;
            uint32_t bf[4][2];
            #pragma unroll
            for (int nt = 0; nt < 4; nt++) {
                const float* bp = Bs + (wn * 32 + nt * 8 + g) * SAS + kb + tig;
                bf[nt][0] = __float_as_uint(bp[0]);
                bf[nt][1] = __float_as_uint(bp[4]);
            }
            #pragma unroll
            for (int mt = 0; mt < 4; mt++) {
                const float* ap0 = As + (wm * 64 + mt * 16 + g) * SAS + kb + tig;
                const float* ap1 = ap0 + 8 * SAS;
                uint32_t a0 = __float_as_uint(ap0[0]);
                uint32_t a1 = __float_as_uint(ap1[0]);
                uint32_t a2 = __float_as_uint(ap0[4]);
                uint32_t a3 = __float_as_uint(ap1[4]);
                #pragma unroll
                for (int nt = 0; nt < 4; nt++)
                    mma_tf32(c[mt][nt], a0, a1, a2, a3, bf[nt][0], bf[nt][1]);
            }
        }

        if (blk < HID / KB - 1) {
            #pragma unroll
            for (int it = 0; it < 4; it++) {
                int row = lrow + it * 32;
                float4 av = ra[it], bv4 = rb[it];
                av.x = f2tff(av.x); av.y = f2tff(av.y); av.z = f2tff(av.z); av.w = f2tff(av.w);
                bv4.x = f2tff(bv4.x); bv4.y = f2tff(bv4.y); bv4.z = f2tff(bv4.z); bv4.w = f2tff(bv4.w);
                *(float4*)(Abuf[1 - p] + row * SAS + lc4) = av;
                *(float4*)(Bbuf[1 - p] + row * SAS + lc4) = bv4;
            }
            __syncthreads();
        }
    }

    #pragma unroll
    for (int mt = 0; mt < 4; mt++) {
        int r0 = m0 + wm * 64 + mt * 16 + g;
        #pragma unroll
        for (int half = 0; half < 2; half++) {
            int r = r0 + half * 8;
            int b = r >> 5;
            int l = r & 31;
            float* obase = out + (((size_t)b * NH) * LQ + l) * HD;
            #pragma unroll
            for (int nt = 0; nt < 4; nt++) {
                int n = n0 + wn * 32 + nt * 8 + tig * 2;
                int h = n >> 6;
                int d = n & 63;
                float2 v;
                v.x = c[mt][nt][half * 2 + 0] + bias[n];
                v.y = c[mt][nt][half * 2 + 1] + bias[n + 1];
                *(float2*)(obase + (size_t)h * LQ * HD + d) = v;
            }
        }
    }
}

// ---------------------------------------------------------------------------
// Attention, 2-term compensated tf32 MMAs + cp.async double-buffered K/V.
// One CTA per (b,h), 128 threads = 4 warps.
// ---------------------------------------------------------------------------
#define SD 68
// dynamic smem layout (floats)
#define QP_OFF   0
#define K0_OFF   (LQ*SD)              // 2176
#define K1_OFF   (K0_OFF + 64*SD)     // 6528
#define V0_OFF   (K1_OFF + 64*SD)     // 10880
#define V1_OFF   (V0_OFF + 64*SD)     // 15232
#define MK_OFF   (V1_OFF + 64*SD)     // 19584
#define AL_OFF   (MK_OFF + TOTKV + 64)// 20320
#define LS_OFF   (AL_OFF + LQ)        // 20352
#define ATTN_SMF (LS_OFF + LQ)        // 20384 floats = 81536 B

__device__ __forceinline__ void tile_ptrs(
    int t, int b, int h, int bh,
    const float* c0k, const float* c0v,
    const float* c1k, const float* c1v,
    const float** kp, const float** vp, int* rows, int* kvbase)
{
    if (t < 8) {
        size_t off = (((size_t)(b % BSC) * NH + h) * LEN0 + t * 64) * HD;
        *kp = c0k + off; *vp = c0v + off; *rows = 64; *kvbase = t * 64;
    } else if (t < 10) {
        size_t off = (((size_t)b * NH + h) * LEN1 + (t - 8) * 64) * HD;
        *kp = c1k + off; *vp = c1v + off; *rows = 64; *kvbase = LEN0 + (t - 8) * 64;
    } else {
        size_t off = (size_t)bh * (LQ * HD);
        *kp = g_k + off; *vp = g_v + off; *rows = 32; *kvbase = LEN0 + LEN1;
    }
}

__global__ __launch_bounds__(128) void attn_mma(
    const float* __restrict__ c0k, const float* __restrict__ c0v,
    const float* __restrict__ c1k, const float* __restrict__ c1v,
    const float* __restrict__ mask, float* __restrict__ out)
{
    extern __shared__ float sm[];
    const int bh = blockIdx.x;
    const int b = bh / NH;
    const int h = bh % NH;

    float* qp_s = sm + QP_OFF;
    float* mask_s = sm + MK_OFF;
    float* alpha_s = sm + AL_OFF;
    float* l_s = sm + LS_OFF;
    const uint32_t smb = smem_u32(sm);

    const int tid = threadIdx.x;
    const int wid = tid >> 5;
    const int lane = tid & 31;
    const int g = lane >> 2;
    const int tig = lane & 3;
    const int srow = tid >> 2;
    const int q4 = tid & 3;

    // issue cp.async for tile 0 into buffer 0
    {
        const float* kp; const float* vp; int rows, kvb;
        tile_ptrs(0, b, h, bh, c0k, c0v, c1k, c1v, &kp, &vp, &rows, &kvb);
        uint32_t kb = smb + K0_OFF * 4;
        uint32_t vb = smb + V0_OFF * 4;
        #pragma unroll
        for (int it = 0; it < 8; it++) {
            int i = tid + it * 128;
            int row = i >> 4;
            int c4 = (i & 15) * 4;
            CP_A16(kb + (row * SD + c4) * 4, kp + row * HD + c4);
            CP_A16(vb + (row * SD + c4) * 4, vp + row * HD + c4);
        }
        CP_COMMIT();
    }

    // load Q (scaled + rounded) and mask
    {
        const float* qp = g_q + (size_t)bh * (LQ * HD);
        #pragma unroll
        for (int it = 0; it < 4; it++) {
            int i = tid + it * 128;
            int row = i >> 4;
            int c4 = (i & 15) * 4;
            float4 v = *(const float4*)(qp + row * HD + c4);
            v.x = f2tff(v.x * 0.125f); v.y = f2tff(v.y * 0.125f);
            v.z = f2tff(v.z * 0.125f); v.w = f2tff(v.w * 0.125f);
            *(float4*)(qp_s + row * SD + c4) = v;
        }
    }
    for (int i = tid; i < TOTKV; i += 128)
        mask_s[i] = mask[(size_t)b * TOTKV + i];
    if (tid < 64) mask_s[TOTKV + tid] = 0.f;
    __syncthreads();

    // preload Q A-fragments
    uint32_t aq[2][8][4];
    #pragma unroll
    for (int mt = 0; mt < 2; mt++)
        #pragma unroll
        for (int kc = 0; kc < 8; kc++) {
            const float* p = qp_s + (mt * 16 + g) * SD + kc * 8 + tig;
            aq[mt][kc][0] = __float_as_uint(p[0]);
            aq[mt][kc][1] = __float_as_uint(p[8 * SD]);
            aq[mt][kc][2] = __float_as_uint(p[4]);
            aq[mt][kc][3] = __float_as_uint(p[8 * SD + 4]);
        }

    float o[4][4];
    #pragma unroll
    for (int nt = 0; nt < 4; nt++)
        #pragma unroll
        for (int q = 0; q < 4; q++) o[nt][q] = 0.f;

    float m_r = -1e30f, l_r = 0.f;

    for (int t = 0; t < 11; ++t) {
        const int p = t & 1;
        const float* kp; const float* vp; int rows, kvbase;
        tile_ptrs(t, b, h, bh, c0k, c0v, c1k, c1v, &kp, &vp, &rows, &kvbase);

        __syncthreads();   // prior iteration's reads of buf[1-p] complete

        if (t < 10) {      // prefetch tile t+1 into buffer 1-p
            const float* kp2; const float* vp2; int rows2, kvb2;
            tile_ptrs(t + 1, b, h, bh, c0k, c0v, c1k, c1v, &kp2, &vp2, &rows2, &kvb2);
            uint32_t kb = smb + (p ? K0_OFF : K1_OFF) * 4;
            uint32_t vb = smb + (p ? V0_OFF : V1_OFF) * 4;
            int nld = rows2 * 16 / 128;
            for (int it = 0; it < nld; it++) {
                int i = tid + it * 128;
                int row = i >> 4;
                int c4 = (i & 15) * 4;
                CP_A16(kb + (row * SD + c4) * 4, kp2 + row * HD + c4);
                CP_A16(vb + (row * SD + c4) * 4, vp2 + row * HD + c4);
            }
            CP_COMMIT();
            CP_WAIT(1);    // tile t's group done
        } else {
            CP_WAIT(0);
        }
        __syncthreads();   // tile t visible to all

        const float* k_s = sm + (p ? K1_OFF : K0_OFF);
        const float* v_s = sm + (p ? V1_OFF : V0_OFF);

        // ---- QK: s = q_tf32 . (k_hi + k_lo) ----
        float s[2][2][4];
        #pragma unroll
        for (int mt = 0; mt < 2; mt++)
            #pragma unroll
            for (int nt = 0; nt < 2; nt++)
                #pragma unroll
                for (int q = 0; q < 4; q++) s[mt][nt][q] = 0.f;

        #pragma unroll
        for (int kc = 0; kc < 8; kc++) {
            #pragma unroll
            for (int nt = 0; nt < 2; nt++) {
                const float* bp = k_s + (wid * 16 + nt * 8 + g) * SD + kc * 8 + tig;
                float b0 = bp[0], b1 = bp[4];
                uint32_t bh0 = f2tf(b0), bh1 = f2tf(b1);
                uint32_t bl0 = __float_as_uint(b0 - __uint_as_float(bh0));
                uint32_t bl1 = __float_as_uint(b1 - __uint_as_float(bh1));
                #pragma unroll
                for (int mt = 0; mt < 2; mt++) {
                    const uint32_t* a = aq[mt][kc];
                    mma_tf32(s[mt][nt], a[0], a[1], a[2], a[3], bh0, bh1);
                    mma_tf32(s[mt][nt], a[0], a[1], a[2], a[3], bl0, bl1);
                }
            }
        }

        #pragma unroll
        for (int mt = 0; mt < 2; mt++)
            #pragma unroll
            for (int nt = 0; nt < 2; nt++) {
                int cb = wid * 16 + nt * 8 + 2 * tig;
                float* p0 = qp_s + (mt * 16 + g) * SD + cb;
                *(float2*)p0 = make_float2(s[mt][nt][0], s[mt][nt][1]);
                *(float2*)(p0 + 8 * SD) = make_float2(s[mt][nt][2], s[mt][nt][3]);
            }
        __syncthreads();

        // ---- softmax ----
        {
            float pv[16];
            float tmax = -1e30f;
            #pragma unroll
            for (int j4 = 0; j4 < 4; j4++) {
                float4 sv = *(const float4*)(qp_s + srow * SD + q4 * 16 + j4 * 4);
                float4 mv = *(const float4*)(mask_s + kvbase + q4 * 16 + j4 * 4);
                float vv[4] = {sv.x + mv.x, sv.y + mv.y, sv.z + mv.z, sv.w + mv.w};
                #pragma unroll
                for (int e = 0; e < 4; e++) {
                    int jc = q4 * 16 + j4 * 4 + e;
                    float val = (jc < rows) ? vv[e] : -1e30f;
                    pv[j4 * 4 + e] = val;
                    tmax = fmaxf(tmax, val);
                }
            }
            tmax = fmaxf(tmax, __shfl_xor_sync(0xffffffffu, tmax, 1));
            tmax = fmaxf(tmax, __shfl_xor_sync(0xffffffffu, tmax, 2));
            float m_new = fmaxf(m_r, tmax);
            float alpha = __expf(m_r - m_new);
            float psum = 0.f;
            #pragma unroll
            for (int j = 0; j < 16; j++) {
                pv[j] = f2tff(__expf(pv[j] - m_new));
                psum += pv[j];
            }
            psum += __shfl_xor_sync(0xffffffffu, psum, 1);
            psum += __shfl_xor_sync(0xffffffffu, psum, 2);
            l_r = l_r * alpha + psum;
            m_r = m_new;
            #pragma unroll
            for (int j4 = 0; j4 < 4; j4++)
                *(float4*)(qp_s + srow * SD + q4 * 16 + j4 * 4) =
                    make_float4(pv[j4 * 4 + 0], pv[j4 * 4 + 1],
                                pv[j4 * 4 + 2], pv[j4 * 4 + 3]);
            if (q4 == 0) alpha_s[srow] = alpha;
        }
        __syncthreads();

        // ---- PV: O^T += (v_hi + v_lo) . p_tf32 ----
        #pragma unroll
        for (int nt = 0; nt < 4; nt++) {
            float la0 = alpha_s[nt * 8 + 2 * tig];
            float la1 = alpha_s[nt * 8 + 2 * tig + 1];
            o[nt][0] *= la0; o[nt][1] *= la1;
            o[nt][2] *= la0; o[nt][3] *= la1;
        }
        #pragma unroll
        for (int kc = 0; kc < 8; kc++) {
            const float* vb = v_s + (kc * 8 + tig) * SD + wid * 16 + g;
            float a0 = vb[0], a1 = vb[8], a2 = vb[4 * SD], a3 = vb[4 * SD + 8];
            uint32_t h0 = f2tf(a0), h1 = f2tf(a1), h2 = f2tf(a2), h3 = f2tf(a3);
            uint32_t l0 = __float_as_uint(a0 - __uint_as_float(h0));
            uint32_t l1 = __float_as_uint(a1 - __uint_as_float(h1));
            uint32_t l2 = __float_as_uint(a2 - __uint_as_float(h2));
            uint32_t l3 = __float_as_uint(a3 - __uint_as_float(h3));
            #pragma unroll
            for (int nt = 0; nt < 4; nt++) {
                const float* pb = qp_s + (nt * 8 + g) * SD + kc * 8 + tig;
                uint32_t p0 = __float_as_uint(pb[0]);
                uint32_t p1 = __float_as_uint(pb[4]);
                mma_tf32(o[nt], h0, h1, h2, h3, p0, p1);
                mma_tf32(o[nt], l0, l1, l2, l3, p0, p1);
            }
        }
    }

    if (q4 == 0) l_s[srow] = l_r;
    __syncthreads();

    // normalize and stage O^T into k-buffer 0 (stride 33)
    float* ot_s = sm + K0_OFF;
    #pragma unroll
    for (int nt = 0; nt < 4; nt++) {
        int q0 = nt * 8 + 2 * tig;
        float il0 = 1.f / l_s[q0];
        float il1 = 1.f / l_s[q0 + 1];
        int d0 = wid * 16 + g;
        ot_s[d0 * 33 + q0]     = o[nt][0] * il0;
        ot_s[d0 * 33 + q0 + 1] = o[nt][1] * il1;
        ot_s[(d0 + 8) * 33 + q0]     = o[nt][2] * il0;
        ot_s[(d0 + 8) * 33 + q0 + 1] = o[nt][3] * il1;
    }
    __syncthreads();

    {
        int q = tid >> 2;
        int dp = (tid & 3) * 16;
        float* op = out + ((size_t)(b * LQ + q)) * HID + h * HD + dp;
        #pragma unroll
        for (int j = 0; j < 4; j++) {
            float4 vv;
            vv.x = ot_s[(dp + 4 * j + 0) * 33 + q];
            vv.y = ot_s[(dp + 4 * j + 1) * 33 + q];
            vv.z = ot_s[(dp + 4 * j + 2) * 33 + q];
            vv.w = ot_s[(dp + 4 * j + 3) * 33 + q];
            *(float4*)(op + 4 * j) = vv;
        }
    }
}

extern "C" void kernel_launch(void* const* d_in, const int* in_sizes, int n_in,
                              void* d_out, int out_size)
{
    const float* hs   = (const float*)d_in[0];
    const float* mask = (const float*)d_in[1];
    const float* c0k  = (const float*)d_in[2];
    const float* c0v  = (const float*)d_in[3];
    const float* c1k  = (const float*)d_in[4];
    const float* c1v  = (const float*)d_in[5];
    const float* Wq   = (const float*)d_in[6];
    const float* bq   = (const float*)d_in[7];
    const float* Wk   = (const float*)d_in[8];
    const float* bk   = (const float*)d_in[9];
    const float* Wv   = (const float*)d_in[10];
    const float* bv   = (const float*)d_in[11];
    float* out = (float*)d_out;

    const int gemm_smem = 4 * SMG * 4;        // 73728 B
    const int attn_smem = ATTN_SMF * 4;       // 81536 B
    cudaFuncSetAttribute(qkv_gemm_mma, cudaFuncAttributeMaxDynamicSharedMemorySize, gemm_smem);
    cudaFuncSetAttribute(attn_mma, cudaFuncAttributeMaxDynamicSharedMemorySize, attn_smem);

    dim3 tgrid(HID / 32, HID / 32, 3);
    transpose_w<<<tgrid, dim3(32, 8)>>>(Wq, Wk, Wv);

    dim3 ggrid(MROWS / 128, HID / 128, 3);
    qkv_gemm_mma<<<ggrid, 256, gemm_smem>>>(hs, bq, bk, bv);

    attn_mma<<<FULLB * NH, 128, attn_smem>>>(c0k, c0v, c1k, c1v, mask, out);
}

// round 15
// speedup vs baseline: 1.4129x; 1.4129x over previous
#include <cuda_runtime.h>
#include <cuda_fp16.h>
#include <cstdint>

#define NH 12
#define HD 64
#define HID 768
#define BSC 8
#define FULLB 240
#define LQ 32
#define LEN0 512
#define LEN1 128
#define TOTKV 672
#define MROWS (FULLB*LQ)   // 7680

// Scratch
__device__ float g_q[FULLB*NH*LQ*HD];
__device__ float g_k[FULLB*NH*LQ*HD];
__device__ float g_v[FULLB*NH*LQ*HD];
__device__ float g_wt[3*HID*HID];     // Wt[n][k] = W[k][n]

__device__ __forceinline__ void mma_tf32(float* c, uint32_t a0, uint32_t a1,
                                         uint32_t a2, uint32_t a3,
                                         uint32_t b0, uint32_t b1) {
    asm volatile(
        "mma.sync.aligned.m16n8k8.row.col.f32.tf32.tf32.f32 "
        "{%0,%1,%2,%3}, {%4,%5,%6,%7}, {%8,%9}, {%0,%1,%2,%3};"
        : "+f"(c[0]), "+f"(c[1]), "+f"(c[2]), "+f"(c[3])
        : "r"(a0), "r"(a1), "r"(a2), "r"(a3), "r"(b0), "r"(b1));
}
__device__ __forceinline__ void mma_f16(float* c, uint32_t a0, uint32_t a1,
                                        uint32_t a2, uint32_t a3,
                                        uint32_t b0, uint32_t b1) {
    asm volatile(
        "mma.sync.aligned.m16n8k16.row.col.f32.f16.f16.f32 "
        "{%0,%1,%2,%3}, {%4,%5,%6,%7}, {%8,%9}, {%0,%1,%2,%3};"
        : "+f"(c[0]), "+f"(c[1]), "+f"(c[2]), "+f"(c[3])
        : "r"(a0), "r"(a1), "r"(a2), "r"(a3), "r"(b0), "r"(b1));
}
__device__ __forceinline__ uint32_t f2tf(float x) {
    uint32_t r;
    asm("cvt.rna.tf32.f32 %0, %1;" : "=r"(r) : "f"(x));
    return r;
}
__device__ __forceinline__ float f2tff(float x) {
    return __uint_as_float(f2tf(x));
}
__device__ __forceinline__ uint32_t pack_h2(float x, float y) {
    __half2 h = __floats2half2_rn(x, y);
    return *(uint32_t*)&h;
}

// ---------------------------------------------------------------------------
// Weight transpose: Wt[n][k] = W[k][n]
// ---------------------------------------------------------------------------
__global__ __launch_bounds__(256) void transpose_w(
    const float* __restrict__ Wq, const float* __restrict__ Wk, const float* __restrict__ Wv)
{
    const float* W = blockIdx.z == 0 ? Wq : blockIdx.z == 1 ? Wk : Wv;
    float* Wt = g_wt + (size_t)blockIdx.z * HID * HID;
    __shared__ float ts[32][33];
    int tx = threadIdx.x, ty = threadIdx.y;
    int x = blockIdx.x * 32 + tx;
    int y0 = blockIdx.y * 32;
    #pragma unroll
    for (int i = 0; i < 4; i++)
        ts[ty + 8 * i][tx] = W[(size_t)(y0 + ty + 8 * i) * HID + x];
    __syncthreads();
    int x2 = blockIdx.y * 32 + tx;
    int y2 = blockIdx.x * 32;
    #pragma unroll
    for (int i = 0; i < 4; i++)
        Wt[(size_t)(y2 + ty + 8 * i) * HID + x2] = ts[tx][ty + 8 * i];
}

// ---------------------------------------------------------------------------
// FP16 m16n8k16 QKV GEMM: C(7680x768) = A @ W + bias.
// CTA 128x128, 8 warps (2m x 4n), KB=64, fp32 accum, rna fp16 inputs.
// Smem rows: 64 halves = 32 b32 words + 4 pad (stride 36 -> conflict-free frags).
// ---------------------------------------------------------------------------
#define KB 64
#define SAS 36   // b32 words per smem row

__global__ __launch_bounds__(256) void qkv_gemm_mma(
    const float* __restrict__ A,
    const float* __restrict__ bq, const float* __restrict__ bk, const float* __restrict__ bv)
{
    __shared__ uint32_t As[128 * SAS];
    __shared__ uint32_t Bs[128 * SAS];

    const int tid = threadIdx.x;
    const int wid = tid >> 5;
    const int lane = tid & 31;
    const int g = lane >> 2;
    const int tig = lane & 3;
    const int wm = wid & 1;
    const int wn = wid >> 1;

    const int z = blockIdx.z;
    const float* bias = z == 0 ? bq : z == 1 ? bk : bv;
    float* out = z == 0 ? g_q : z == 1 ? g_k : g_v;
    const float* Wt = g_wt + (size_t)z * HID * HID;
    const int m0 = blockIdx.x * 128;
    const int n0 = blockIdx.y * 128;

    float c[4][4][4];
    #pragma unroll
    for (int mt = 0; mt < 4; mt++)
        #pragma unroll
        for (int nt = 0; nt < 4; nt++)
            #pragma unroll
            for (int q = 0; q < 4; q++) c[mt][nt][q] = 0.f;

    for (int k0 = 0; k0 < HID; k0 += KB) {   // 12 blocks
        __syncthreads();
        #pragma unroll
        for (int it = 0; it < 8; it++) {
            int i = tid + it * 256;        // 0..2047
            int row = i >> 4;              // 0..127
            int ch = (i & 15) * 4;         // half-index 0..60
            float4 av = *(const float4*)(A  + (size_t)(m0 + row) * HID + k0 + ch);
            float4 bv4 = *(const float4*)(Wt + (size_t)(n0 + row) * HID + k0 + ch);
            uint2 ap = make_uint2(pack_h2(av.x, av.y), pack_h2(av.z, av.w));
            uint2 bp = make_uint2(pack_h2(bv4.x, bv4.y), pack_h2(bv4.z, bv4.w));
            *(uint2*)(As + row * SAS + (ch >> 1)) = ap;
            *(uint2*)(Bs + row * SAS + (ch >> 1)) = bp;
        }
        __syncthreads();

        #pragma unroll
        for (int ks = 0; ks < 4; ks++) {   // K=16 each
            const int kb = ks * 8;         // b32 word offset
            uint32_t bf[4][2];
            #pragma unroll
            for (int nt = 0; nt < 4; nt++) {
                const uint32_t* bp = Bs + (wn * 32 + nt * 8 + g) * SAS + kb + tig;
                bf[nt][0] = bp[0];
                bf[nt][1] = bp[4];
            }
            #pragma unroll
            for (int mt = 0; mt < 4; mt++) {
                const uint32_t* ap0 = As + (wm * 64 + mt * 16 + g) * SAS + kb + tig;
                const uint32_t* ap1 = ap0 + 8 * SAS;
                uint32_t a0 = ap0[0];
                uint32_t a1 = ap1[0];
                uint32_t a2 = ap0[4];
                uint32_t a3 = ap1[4];
                #pragma unroll
                for (int nt = 0; nt < 4; nt++)
                    mma_f16(c[mt][nt], a0, a1, a2, a3, bf[nt][0], bf[nt][1]);
            }
        }
    }

    #pragma unroll
    for (int mt = 0; mt < 4; mt++) {
        int r0 = m0 + wm * 64 + mt * 16 + g;
        #pragma unroll
        for (int half = 0; half < 2; half++) {
            int r = r0 + half * 8;
            int b = r >> 5;
            int l = r & 31;
            float* obase = out + (((size_t)b * NH) * LQ + l) * HD;
            #pragma unroll
            for (int nt = 0; nt < 4; nt++) {
                int n = n0 + wn * 32 + nt * 8 + tig * 2;
                int h = n >> 6;
                int d = n & 63;
                float2 v;
                v.x = c[mt][nt][half * 2 + 0] + bias[n];
                v.y = c[mt][nt][half * 2 + 1] + bias[n + 1];
                *(float2*)(obase + (size_t)h * LQ * HD + d) = v;
            }
        }
    }
}

// ---------------------------------------------------------------------------
// Attention (R10 structure): 2-term QK, 1-term PV, tf32 mma.sync.
// One CTA per (b,h), 128 threads = 4 warps.
// ---------------------------------------------------------------------------
#define SD 68

__global__ __launch_bounds__(128) void attn_mma(
    const float* __restrict__ c0k, const float* __restrict__ c0v,
    const float* __restrict__ c1k, const float* __restrict__ c1v,
    const float* __restrict__ mask, float* __restrict__ out)
{
    const int bh = blockIdx.x;
    const int b = bh / NH;
    const int h = bh % NH;

    __shared__ float qp_s[LQ * SD];      // Q staging (rounded), then P
    __shared__ float k_s[64 * SD];       // K tile; O^T staging at the end
    __shared__ float v_s[64 * SD];       // V tile
    __shared__ float mask_s[TOTKV + 64];
    __shared__ float alpha_s[LQ];
    __shared__ float l_s[LQ];

    const int tid = threadIdx.x;
    const int wid = tid >> 5;
    const int lane = tid & 31;
    const int g = lane >> 2;
    const int tig = lane & 3;
    const int srow = tid >> 2;
    const int q4 = tid & 3;

    // load Q (32x64), fold in 1/sqrt(64), round to tf32 once
    {
        const float* qp = g_q + (size_t)bh * (LQ * HD);
        #pragma unroll
        for (int it = 0; it < 4; it++) {
            int i = tid + it * 128;
            int row = i >> 4;
            int c4 = (i & 15) * 4;
            float4 v = *(const float4*)(qp + row * HD + c4);
            v.x = f2tff(v.x * 0.125f); v.y = f2tff(v.y * 0.125f);
            v.z = f2tff(v.z * 0.125f); v.w = f2tff(v.w * 0.125f);
            *(float4*)(qp_s + row * SD + c4) = v;
        }
    }
    for (int i = tid; i < TOTKV; i += 128)
        mask_s[i] = mask[(size_t)b * TOTKV + i];
    if (tid < 64) mask_s[TOTKV + tid] = 0.f;
    __syncthreads();

    // preload Q A-fragments (tf32-valued bits)
    uint32_t aq[2][8][4];
    #pragma unroll
    for (int mt = 0; mt < 2; mt++)
        #pragma unroll
        for (int kc = 0; kc < 8; kc++) {
            const float* p = qp_s + (mt * 16 + g) * SD + kc * 8 + tig;
            aq[mt][kc][0] = __float_as_uint(p[0]);
            aq[mt][kc][1] = __float_as_uint(p[8 * SD]);
            aq[mt][kc][2] = __float_as_uint(p[4]);
            aq[mt][kc][3] = __float_as_uint(p[8 * SD + 4]);
        }

    float o[4][4];
    #pragma unroll
    for (int nt = 0; nt < 4; nt++)
        #pragma unroll
        for (int q = 0; q < 4; q++) o[nt][q] = 0.f;

    float m_r = -1e30f, l_r = 0.f;

    for (int t = 0; t < 11; ++t) {
        const float* kp; const float* vp; int rows, kvbase;
        if (t < 8) {
            size_t off = (((size_t)(b % BSC) * NH + h) * LEN0 + t * 64) * HD;
            kp = c0k + off; vp = c0v + off; rows = 64; kvbase = t * 64;
        } else if (t < 10) {
            size_t off = (((size_t)b * NH + h) * LEN1 + (t - 8) * 64) * HD;
            kp = c1k + off; vp = c1v + off; rows = 64; kvbase = LEN0 + (t - 8) * 64;
        } else {
            size_t off = (size_t)bh * (LQ * HD);
            kp = g_k + off; vp = g_v + off; rows = 32; kvbase = LEN0 + LEN1;
        }

        __syncthreads();
        {
            int nld = rows * 16 / 128;
            for (int it = 0; it < nld; it++) {
                int i = tid + it * 128;
                int row = i >> 4;
                int c4 = (i & 15) * 4;
                *(float4*)(k_s + row * SD + c4) = *(const float4*)(kp + row * HD + c4);
                *(float4*)(v_s + row * SD + c4) = *(const float4*)(vp + row * HD + c4);
            }
        }
        __syncthreads();

        // ---- QK: s = q_tf32 . (k_hi + k_lo), 2 MMAs ----
        float s[2][2][4];
        #pragma unroll
        for (int mt = 0; mt < 2; mt++)
            #pragma unroll
            for (int nt = 0; nt < 2; nt++)
                #pragma unroll
                for (int q = 0; q < 4; q++) s[mt][nt][q] = 0.f;

        #pragma unroll
        for (int kc = 0; kc < 8; kc++) {
            #pragma unroll
            for (int nt = 0; nt < 2; nt++) {
                const float* bp = k_s + (wid * 16 + nt * 8 + g) * SD + kc * 8 + tig;
                float b0 = bp[0], b1 = bp[4];
                uint32_t bh0 = f2tf(b0), bh1 = f2tf(b1);
                uint32_t bl0 = __float_as_uint(b0 - __uint_as_float(bh0));
                uint32_t bl1 = __float_as_uint(b1 - __uint_as_float(bh1));
                #pragma unroll
                for (int mt = 0; mt < 2; mt++) {
                    const uint32_t* a = aq[mt][kc];
                    mma_tf32(s[mt][nt], a[0], a[1], a[2], a[3], bh0, bh1);
                    mma_tf32(s[mt][nt], a[0], a[1], a[2], a[3], bl0, bl1);
                }
            }
        }

        #pragma unroll
        for (int mt = 0; mt < 2; mt++)
            #pragma unroll
            for (int nt = 0; nt < 2; nt++) {
                int cb = wid * 16 + nt * 8 + 2 * tig;
                float* p0 = qp_s + (mt * 16 + g) * SD + cb;
                *(float2*)p0 = make_float2(s[mt][nt][0], s[mt][nt][1]);
                *(float2*)(p0 + 8 * SD) = make_float2(s[mt][nt][2], s[mt][nt][3]);
            }
        __syncthreads();

        // ---- softmax ----
        {
            float pv[16];
            float tmax = -1e30f;
            #pragma unroll
            for (int j4 = 0; j4 < 4; j4++) {
                float4 sv = *(const float4*)(qp_s + srow * SD + q4 * 16 + j4 * 4);
                float4 mv = *(const float4*)(mask_s + kvbase + q4 * 16 + j4 * 4);
                float vv[4] = {sv.x + mv.x, sv.y + mv.y, sv.z + mv.z, sv.w + mv.w};
                #pragma unroll
                for (int e = 0; e < 4; e++) {
                    int jc = q4 * 16 + j4 * 4 + e;
                    float val = (jc < rows) ? vv[e] : -1e30f;
                    pv[j4 * 4 + e] = val;
                    tmax = fmaxf(tmax, val);
                }
            }
            tmax = fmaxf(tmax, __shfl_xor_sync(0xffffffffu, tmax, 1));
            tmax = fmaxf(tmax, __shfl_xor_sync(0xffffffffu, tmax, 2));
            float m_new = fmaxf(m_r, tmax);
            float alpha = __expf(m_r - m_new);
            float psum = 0.f;
            #pragma unroll
            for (int j = 0; j < 16; j++) {
                pv[j] = f2tff(__expf(pv[j] - m_new));
                psum += pv[j];
            }
            psum += __shfl_xor_sync(0xffffffffu, psum, 1);
            psum += __shfl_xor_sync(0xffffffffu, psum, 2);
            l_r = l_r * alpha + psum;
            m_r = m_new;
            #pragma unroll
            for (int j4 = 0; j4 < 4; j4++)
                *(float4*)(qp_s + srow * SD + q4 * 16 + j4 * 4) =
                    make_float4(pv[j4 * 4 + 0], pv[j4 * 4 + 1],
                                pv[j4 * 4 + 2], pv[j4 * 4 + 3]);
            if (q4 == 0) alpha_s[srow] = alpha;
        }
        __syncthreads();

        // ---- PV (1-term): O^T += v_rna . p_tf32 ----
        #pragma unroll
        for (int nt = 0; nt < 4; nt++) {
            float la0 = alpha_s[nt * 8 + 2 * tig];
            float la1 = alpha_s[nt * 8 + 2 * tig + 1];
            o[nt][0] *= la0; o[nt][1] *= la1;
            o[nt][2] *= la0; o[nt][3] *= la1;
        }
        #pragma unroll
        for (int kc = 0; kc < 8; kc++) {
            const float* vb = v_s + (kc * 8 + tig) * SD + wid * 16 + g;
            uint32_t h0 = f2tf(vb[0]);
            uint32_t h1 = f2tf(vb[8]);
            uint32_t h2v = f2tf(vb[4 * SD]);
            uint32_t h3 = f2tf(vb[4 * SD + 8]);
            #pragma unroll
            for (int nt = 0; nt < 4; nt++) {
                const float* pb = qp_s + (nt * 8 + g) * SD + kc * 8 + tig;
                uint32_t p0 = __float_as_uint(pb[0]);
                uint32_t p1 = __float_as_uint(pb[4]);
                mma_tf32(o[nt], h0, h1, h2v, h3, p0, p1);
            }
        }
    }

    if (q4 == 0) l_s[srow] = l_r;
    __syncthreads();

    // normalize and stage O^T into k_s (stride 33)
    #pragma unroll
    for (int nt = 0; nt < 4; nt++) {
        int q0 = nt * 8 + 2 * tig;
        float il0 = 1.f / l_s[q0];
        float il1 = 1.f / l_s[q0 + 1];
        int d0 = wid * 16 + g;
        k_s[d0 * 33 + q0]     = o[nt][0] * il0;
        k_s[d0 * 33 + q0 + 1] = o[nt][1] * il1;
        k_s[(d0 + 8) * 33 + q0]     = o[nt][2] * il0;
        k_s[(d0 + 8) * 33 + q0 + 1] = o[nt][3] * il1;
    }
    __syncthreads();

    {
        int q = tid >> 2;
        int dp = (tid & 3) * 16;
        float* op = out + ((size_t)(b * LQ + q)) * HID + h * HD + dp;
        #pragma unroll
        for (int j = 0; j < 4; j++) {
            float4 vv;
            vv.x = k_s[(dp + 4 * j + 0) * 33 + q];
            vv.y = k_s[(dp + 4 * j + 1) * 33 + q];
            vv.z = k_s[(dp + 4 * j + 2) * 33 + q];
            vv.w = k_s[(dp + 4 * j + 3) * 33 + q];
            *(float4*)(op + 4 * j) = vv;
        }
    }
}

extern "C" void kernel_launch(void* const* d_in, const int* in_sizes, int n_in,
                              void* d_out, int out_size)
{
    const float* hs   = (const float*)d_in[0];
    const float* mask = (const float*)d_in[1];
    const float* c0k  = (const float*)d_in[2];
    const float* c0v  = (const float*)d_in[3];
    const float* c1k  = (const float*)d_in[4];
    const float* c1v  = (const float*)d_in[5];
    const float* Wq   = (const float*)d_in[6];
    const float* bq   = (const float*)d_in[7];
    const float* Wk   = (const float*)d_in[8];
    const float* bk   = (const float*)d_in[9];
    const float* Wv   = (const float*)d_in[10];
    const float* bv   = (const float*)d_in[11];
    float* out = (float*)d_out;

    dim3 tgrid(HID / 32, HID / 32, 3);
    transpose_w<<<tgrid, dim3(32, 8)>>>(Wq, Wk, Wv);

    dim3 ggrid(MROWS / 128, HID / 128, 3);
    qkv_gemm_mma<<<ggrid, 256>>>(hs, bq, bk, bv);

    attn_mma<<<FULLB * NH, 128>>>(c0k, c0v, c1k, c1v, mask, out);
}

// round 16
// speedup vs baseline: 1.6050x; 1.1360x over previous
#include <cuda_runtime.h>
#include <cuda_fp16.h>
#include <cstdint>

#define NH 12
#define HD 64
#define HID 768
#define BSC 8
#define FULLB 240
#define LQ 32
#define LEN0 512
#define LEN1 128
#define TOTKV 672
#define MROWS (FULLB*LQ)   // 7680

// Scratch
__device__ float g_q[FULLB*NH*LQ*HD];
__device__ float g_k[FULLB*NH*LQ*HD];
__device__ float g_v[FULLB*NH*LQ*HD];
__device__ float g_wt[3*HID*HID];     // Wt[n][k] = W[k][n]

__device__ __forceinline__ void mma_f16(float* c, uint32_t a0, uint32_t a1,
                                        uint32_t a2, uint32_t a3,
                                        uint32_t b0, uint32_t b1) {
    asm volatile(
        "mma.sync.aligned.m16n8k16.row.col.f32.f16.f16.f32 "
        "{%0,%1,%2,%3}, {%4,%5,%6,%7}, {%8,%9}, {%0,%1,%2,%3};"
        : "+f"(c[0]), "+f"(c[1]), "+f"(c[2]), "+f"(c[3])
        : "r"(a0), "r"(a1), "r"(a2), "r"(a3), "r"(b0), "r"(b1));
}
__device__ __forceinline__ uint32_t pack_h2(float x, float y) {
    __half2 h = __floats2half2_rn(x, y);
    return *(uint32_t*)&h;
}

// ---------------------------------------------------------------------------
// Weight transpose: Wt[n][k] = W[k][n]
// ---------------------------------------------------------------------------
__global__ __launch_bounds__(256) void transpose_w(
    const float* __restrict__ Wq, const float* __restrict__ Wk, const float* __restrict__ Wv)
{
    const float* W = blockIdx.z == 0 ? Wq : blockIdx.z == 1 ? Wk : Wv;
    float* Wt = g_wt + (size_t)blockIdx.z * HID * HID;
    __shared__ float ts[32][33];
    int tx = threadIdx.x, ty = threadIdx.y;
    int x = blockIdx.x * 32 + tx;
    int y0 = blockIdx.y * 32;
    #pragma unroll
    for (int i = 0; i < 4; i++)
        ts[ty + 8 * i][tx] = W[(size_t)(y0 + ty + 8 * i) * HID + x];
    __syncthreads();
    int x2 = blockIdx.y * 32 + tx;
    int y2 = blockIdx.x * 32;
    #pragma unroll
    for (int i = 0; i < 4; i++)
        Wt[(size_t)(y2 + ty + 8 * i) * HID + x2] = ts[tx][ty + 8 * i];
}

// ---------------------------------------------------------------------------
// FP16 m16n8k16 QKV GEMM (R14-proven): CTA 128x128, 8 warps (2m x 4n), KB=64.
// ---------------------------------------------------------------------------
#define KB 64
#define SAS 36   // b32 words per smem row

__global__ __launch_bounds__(256) void qkv_gemm_mma(
    const float* __restrict__ A,
    const float* __restrict__ bq, const float* __restrict__ bk, const float* __restrict__ bv)
{
    __shared__ uint32_t As[128 * SAS];
    __shared__ uint32_t Bs[128 * SAS];

    const int tid = threadIdx.x;
    const int wid = tid >> 5;
    const int lane = tid & 31;
    const int g = lane >> 2;
    const int tig = lane & 3;
    const int wm = wid & 1;
    const int wn = wid >> 1;

    const int z = blockIdx.z;
    const float* bias = z == 0 ? bq : z == 1 ? bk : bv;
    float* out = z == 0 ? g_q : z == 1 ? g_k : g_v;
    const float* Wt = g_wt + (size_t)z * HID * HID;
    const int m0 = blockIdx.x * 128;
    const int n0 = blockIdx.y * 128;

    float c[4][4][4];
    #pragma unroll
    for (int mt = 0; mt < 4; mt++)
        #pragma unroll
        for (int nt = 0; nt < 4; nt++)
            #pragma unroll
            for (int q = 0; q < 4; q++) c[mt][nt][q] = 0.f;

    for (int k0 = 0; k0 < HID; k0 += KB) {
        __syncthreads();
        #pragma unroll
        for (int it = 0; it < 8; it++) {
            int i = tid + it * 256;
            int row = i >> 4;
            int ch = (i & 15) * 4;
            float4 av = *(const float4*)(A  + (size_t)(m0 + row) * HID + k0 + ch);
            float4 bv4 = *(const float4*)(Wt + (size_t)(n0 + row) * HID + k0 + ch);
            uint2 ap = make_uint2(pack_h2(av.x, av.y), pack_h2(av.z, av.w));
            uint2 bp = make_uint2(pack_h2(bv4.x, bv4.y), pack_h2(bv4.z, bv4.w));
            *(uint2*)(As + row * SAS + (ch >> 1)) = ap;
            *(uint2*)(Bs + row * SAS + (ch >> 1)) = bp;
        }
        __syncthreads();

        #pragma unroll
        for (int ks = 0; ks < 4; ks++) {
            const int kb = ks * 8;
            uint32_t bf[4][2];
            #pragma unroll
            for (int nt = 0; nt < 4; nt++) {
                const uint32_t* bp = Bs + (wn * 32 + nt * 8 + g) * SAS + kb + tig;
                bf[nt][0] = bp[0];
                bf[nt][1] = bp[4];
            }
            #pragma unroll
            for (int mt = 0; mt < 4; mt++) {
                const uint32_t* ap0 = As + (wm * 64 + mt * 16 + g) * SAS + kb + tig;
                const uint32_t* ap1 = ap0 + 8 * SAS;
                uint32_t a0 = ap0[0];
                uint32_t a1 = ap1[0];
                uint32_t a2 = ap0[4];
                uint32_t a3 = ap1[4];
                #pragma unroll
                for (int nt = 0; nt < 4; nt++)
                    mma_f16(c[mt][nt], a0, a1, a2, a3, bf[nt][0], bf[nt][1]);
            }
        }
    }

    #pragma unroll
    for (int mt = 0; mt < 4; mt++) {
        int r0 = m0 + wm * 64 + mt * 16 + g;
        #pragma unroll
        for (int half = 0; half < 2; half++) {
            int r = r0 + half * 8;
            int b = r >> 5;
            int l = r & 31;
            float* obase = out + (((size_t)b * NH) * LQ + l) * HD;
            #pragma unroll
            for (int nt = 0; nt < 4; nt++) {
                int n = n0 + wn * 32 + nt * 8 + tig * 2;
                int h = n >> 6;
                int d = n & 63;
                float2 v;
                v.x = c[mt][nt][half * 2 + 0] + bias[n];
                v.y = c[mt][nt][half * 2 + 1] + bias[n + 1];
                *(float2*)(obase + (size_t)h * LQ * HD + d) = v;
            }
        }
    }
}

// ---------------------------------------------------------------------------
// Attention, all-fp16 m16n8k16:
// QK 2-term (K split hi/lo into packed smem at load; Q rna-fp16 in regs).
// PV 1-term (V packed rna on the fly; P packed rna at softmax write).
// One CTA per (b,h), 128 threads = 4 warps.
// ---------------------------------------------------------------------------
#define SD 68
#define SDK 36   // packed K row stride (b32 words)

__global__ __launch_bounds__(128) void attn_mma(
    const float* __restrict__ c0k, const float* __restrict__ c0v,
    const float* __restrict__ c1k, const float* __restrict__ c1v,
    const float* __restrict__ mask, float* __restrict__ out)
{
    const int bh = blockIdx.x;
    const int b = bh / NH;
    const int h = bh % NH;

    __shared__ float    qp_s[LQ * SD];      // Q staging (fp32, x0.125) -> scores -> packed P
    __shared__ uint32_t khi_s[64 * SDK];    // K hi, packed half2 along d
    __shared__ uint32_t klo_s[64 * SDK];    // K lo
    __shared__ float    v_s[64 * SD];       // V fp32 row-major
    __shared__ float    mask_s[TOTKV + 64];
    __shared__ float    alpha_s[LQ];
    __shared__ float    l_s[LQ];

    const int tid = threadIdx.x;
    const int wid = tid >> 5;
    const int lane = tid & 31;
    const int g = lane >> 2;
    const int tig = lane & 3;
    const int srow = tid >> 2;
    const int q4 = tid & 3;

    // load Q (32x64), fold 1/sqrt(64); fp16 rounding happens at fragment pack
    {
        const float* qp = g_q + (size_t)bh * (LQ * HD);
        #pragma unroll
        for (int it = 0; it < 4; it++) {
            int i = tid + it * 128;
            int row = i >> 4;
            int c4 = (i & 15) * 4;
            float4 v = *(const float4*)(qp + row * HD + c4);
            v.x *= 0.125f; v.y *= 0.125f; v.z *= 0.125f; v.w *= 0.125f;
            *(float4*)(qp_s + row * SD + c4) = v;
        }
    }
    for (int i = tid; i < TOTKV; i += 128)
        mask_s[i] = mask[(size_t)b * TOTKV + i];
    if (tid < 64) mask_s[TOTKV + tid] = 0.f;
    __syncthreads();

    // preload Q A-fragments (packed fp16, rna once)
    uint32_t aq[2][4][4];
    #pragma unroll
    for (int mt = 0; mt < 2; mt++)
        #pragma unroll
        for (int kc = 0; kc < 4; kc++) {
            int dbase = kc * 16 + 2 * tig;
            const float* r0 = qp_s + (mt * 16 + g) * SD + dbase;
            const float* r1 = r0 + 8 * SD;
            aq[mt][kc][0] = pack_h2(r0[0], r0[1]);
            aq[mt][kc][1] = pack_h2(r1[0], r1[1]);
            aq[mt][kc][2] = pack_h2(r0[8], r0[9]);
            aq[mt][kc][3] = pack_h2(r1[8], r1[9]);
        }

    float o[4][4];
    #pragma unroll
    for (int nt = 0; nt < 4; nt++)
        #pragma unroll
        for (int q = 0; q < 4; q++) o[nt][q] = 0.f;

    float m_r = -1e30f, l_r = 0.f;

    for (int t = 0; t < 11; ++t) {
        const float* kp; const float* vp; int rows, kvbase;
        if (t < 8) {
            size_t off = (((size_t)(b % BSC) * NH + h) * LEN0 + t * 64) * HD;
            kp = c0k + off; vp = c0v + off; rows = 64; kvbase = t * 64;
        } else if (t < 10) {
            size_t off = (((size_t)b * NH + h) * LEN1 + (t - 8) * 64) * HD;
            kp = c1k + off; vp = c1v + off; rows = 64; kvbase = LEN0 + (t - 8) * 64;
        } else {
            size_t off = (size_t)bh * (LQ * HD);
            kp = g_k + off; vp = g_v + off; rows = 32; kvbase = LEN0 + LEN1;
        }

        __syncthreads();   // prior PV reads done
        {
            int nld = rows * 16 / 128;   // 8 or 4
            for (int it = 0; it < nld; it++) {
                int i = tid + it * 128;
                int row = i >> 4;
                int c4 = (i & 15) * 4;
                float4 kf = *(const float4*)(kp + row * HD + c4);
                *(float4*)(v_s + row * SD + c4) = *(const float4*)(vp + row * HD + c4);
                // split K into fp16 hi + lo, packed pairs along d
                uint32_t h0 = pack_h2(kf.x, kf.y);
                uint32_t h1 = pack_h2(kf.z, kf.w);
                float2 f0 = __half22float2(*(__half2*)&h0);
                float2 f1 = __half22float2(*(__half2*)&h1);
                uint32_t l0 = pack_h2(kf.x - f0.x, kf.y - f0.y);
                uint32_t l1 = pack_h2(kf.z - f1.x, kf.w - f1.y);
                *(uint2*)(khi_s + row * SDK + (c4 >> 1)) = make_uint2(h0, h1);
                *(uint2*)(klo_s + row * SDK + (c4 >> 1)) = make_uint2(l0, l1);
            }
        }
        __syncthreads();

        // ---- QK: s = q_f16 . (k_hi + k_lo), 2 fp16 MMAs per (mt,nt,kc) ----
        float s[2][2][4];
        #pragma unroll
        for (int mt = 0; mt < 2; mt++)
            #pragma unroll
            for (int nt = 0; nt < 2; nt++)
                #pragma unroll
                for (int q = 0; q < 4; q++) s[mt][nt][q] = 0.f;

        #pragma unroll
        for (int kc = 0; kc < 4; kc++) {
            #pragma unroll
            for (int nt = 0; nt < 2; nt++) {
                int kvrow = wid * 16 + nt * 8 + g;
                const uint32_t* hp = khi_s + kvrow * SDK + kc * 8 + tig;
                const uint32_t* lp = klo_s + kvrow * SDK + kc * 8 + tig;
                uint32_t bh0 = hp[0], bh1 = hp[4];
                uint32_t bl0 = lp[0], bl1 = lp[4];
                #pragma unroll
                for (int mt = 0; mt < 2; mt++) {
                    const uint32_t* a = aq[mt][kc];
                    mma_f16(s[mt][nt], a[0], a[1], a[2], a[3], bh0, bh1);
                    mma_f16(s[mt][nt], a[0], a[1], a[2], a[3], bl0, bl1);
                }
            }
        }

        // write raw fp32 scores to qp_s
        #pragma unroll
        for (int mt = 0; mt < 2; mt++)
            #pragma unroll
            for (int nt = 0; nt < 2; nt++) {
                int cb = wid * 16 + nt * 8 + 2 * tig;
                float* p0 = qp_s + (mt * 16 + g) * SD + cb;
                *(float2*)p0 = make_float2(s[mt][nt][0], s[mt][nt][1]);
                *(float2*)(p0 + 8 * SD) = make_float2(s[mt][nt][2], s[mt][nt][3]);
            }
        __syncthreads();

        // ---- softmax; P written back packed-fp16 over the score row ----
        {
            float pv[16];
            float tmax = -1e30f;
            #pragma unroll
            for (int j4 = 0; j4 < 4; j4++) {
                float4 sv = *(const float4*)(qp_s + srow * SD + q4 * 16 + j4 * 4);
                float4 mv = *(const float4*)(mask_s + kvbase + q4 * 16 + j4 * 4);
                float vv[4] = {sv.x + mv.x, sv.y + mv.y, sv.z + mv.z, sv.w + mv.w};
                #pragma unroll
                for (int e = 0; e < 4; e++) {
                    int jc = q4 * 16 + j4 * 4 + e;
                    float val = (jc < rows) ? vv[e] : -1e30f;
                    pv[j4 * 4 + e] = val;
                    tmax = fmaxf(tmax, val);
                }
            }
            tmax = fmaxf(tmax, __shfl_xor_sync(0xffffffffu, tmax, 1));
            tmax = fmaxf(tmax, __shfl_xor_sync(0xffffffffu, tmax, 2));
            float m_new = fmaxf(m_r, tmax);
            float alpha = __expf(m_r - m_new);
            #pragma unroll
            for (int j = 0; j < 16; j++)
                pv[j] = __expf(pv[j] - m_new);

            __syncwarp();   // all score reads done before packed overwrite

            uint32_t* prow = (uint32_t*)(qp_s + srow * SD);
            float psum = 0.f;
            #pragma unroll
            for (int w = 0; w < 8; w++) {
                uint32_t pk = pack_h2(pv[2 * w], pv[2 * w + 1]);
                prow[q4 * 8 + w] = pk;
                float2 f = __half22float2(*(__half2*)&pk);
                psum += f.x + f.y;
            }
            psum += __shfl_xor_sync(0xffffffffu, psum, 1);
            psum += __shfl_xor_sync(0xffffffffu, psum, 2);
            l_r = l_r * alpha + psum;
            m_r = m_new;
            if (q4 == 0) alpha_s[srow] = alpha;
        }
        __syncthreads();

        // ---- PV (1-term fp16): O^T += v_f16 . p_f16 ----
        #pragma unroll
        for (int nt = 0; nt < 4; nt++) {
            float la0 = alpha_s[nt * 8 + 2 * tig];
            float la1 = alpha_s[nt * 8 + 2 * tig + 1];
            o[nt][0] *= la0; o[nt][1] *= la1;
            o[nt][2] *= la0; o[nt][3] *= la1;
        }
        #pragma unroll
        for (int kc = 0; kc < 4; kc++) {
            int kvb = kc * 16 + 2 * tig;
            int d = wid * 16 + g;
            const float* v0 = v_s + kvb * SD + d;
            const float* v1 = v0 + SD;
            const float* v8 = v0 + 8 * SD;
            const float* v9 = v0 + 9 * SD;
            uint32_t a0 = pack_h2(v0[0], v1[0]);
            uint32_t a1 = pack_h2(v0[8], v1[8]);
            uint32_t a2 = pack_h2(v8[0], v9[0]);
            uint32_t a3 = pack_h2(v8[8], v9[8]);
            #pragma unroll
            for (int nt = 0; nt < 4; nt++) {
                const uint32_t* pb = (const uint32_t*)(qp_s + (nt * 8 + g) * SD) + kc * 8 + tig;
                mma_f16(o[nt], a0, a1, a2, a3, pb[0], pb[4]);
            }
        }
    }

    if (q4 == 0) l_s[srow] = l_r;
    __syncthreads();

    // normalize and stage O^T into khi_s region (fp32, stride 33)
    float* ot_s = (float*)khi_s;
    #pragma unroll
    for (int nt = 0; nt < 4; nt++) {
        int q0 = nt * 8 + 2 * tig;
        float il0 = 1.f / l_s[q0];
        float il1 = 1.f / l_s[q0 + 1];
        int d0 = wid * 16 + g;
        ot_s[d0 * 33 + q0]     = o[nt][0] * il0;
        ot_s[d0 * 33 + q0 + 1] = o[nt][1] * il1;
        ot_s[(d0 + 8) * 33 + q0]     = o[nt][2] * il0;
        ot_s[(d0 + 8) * 33 + q0 + 1] = o[nt][3] * il1;
    }
    __syncthreads();

    {
        int q = tid >> 2;
        int dp = (tid & 3) * 16;
        float* op = out + ((size_t)(b * LQ + q)) * HID + h * HD + dp;
        #pragma unroll
        for (int j = 0; j < 4; j++) {
            float4 vv;
            vv.x = ot_s[(dp + 4 * j + 0) * 33 + q];
            vv.y = ot_s[(dp + 4 * j + 1) * 33 + q];
            vv.z = ot_s[(dp + 4 * j + 2) * 33 + q];
            vv.w = ot_s[(dp + 4 * j + 3) * 33 + q];
            *(float4*)(op + 4 * j) = vv;
        }
    }
}

extern "C" void kernel_launch(void* const* d_in, const int* in_sizes, int n_in,
                              void* d_out, int out_size)
{
    const float* hs   = (const float*)d_in[0];
    const float* mask = (const float*)d_in[1];
    const float* c0k  = (const float*)d_in[2];
    const float* c0v  = (const float*)d_in[3];
    const float* c1k  = (const float*)d_in[4];
    const float* c1v  = (const float*)d_in[5];
    const float* Wq   = (const float*)d_in[6];
    const float* bq   = (const float*)d_in[7];
    const float* Wk   = (const float*)d_in[8];
    const float* bk   = (const float*)d_in[9];
    const float* Wv   = (const float*)d_in[10];
    const float* bv   = (const float*)d_in[11];
    float* out = (float*)d_out;

    dim3 tgrid(HID / 32, HID / 32, 3);
    transpose_w<<<tgrid, dim3(32, 8)>>>(Wq, Wk, Wv);

    dim3 ggrid(MROWS / 128, HID / 128, 3);
    qkv_gemm_mma<<<ggrid, 256>>>(hs, bq, bk, bv);

    attn_mma<<<FULLB * NH, 128>>>(c0k, c0v, c1k, c1v, mask, out);
}

// round 17
// speedup vs baseline: 1.8484x; 1.1517x over previous
#include <cuda_runtime.h>
#include <cuda_fp16.h>
#include <cstdint>

#define NH 12
#define HD 64
#define HID 768
#define BSC 8
#define FULLB 240
#define LQ 32
#define LEN0 512
#define LEN1 128
#define TOTKV 672
#define MROWS (FULLB*LQ)   // 7680
#define NPAIR 120

// Scratch
__device__ float g_q[FULLB*NH*LQ*HD];
__device__ float g_k[FULLB*NH*LQ*HD];
__device__ float g_v[FULLB*NH*LQ*HD];
__device__ float g_wt[3*HID*HID];     // Wt[n][k] = W[k][n]

__device__ __forceinline__ void mma_f16(float* c, uint32_t a0, uint32_t a1,
                                        uint32_t a2, uint32_t a3,
                                        uint32_t b0, uint32_t b1) {
    asm volatile(
        "mma.sync.aligned.m16n8k16.row.col.f32.f16.f16.f32 "
        "{%0,%1,%2,%3}, {%4,%5,%6,%7}, {%8,%9}, {%0,%1,%2,%3};"
        : "+f"(c[0]), "+f"(c[1]), "+f"(c[2]), "+f"(c[3])
        : "r"(a0), "r"(a1), "r"(a2), "r"(a3), "r"(b0), "r"(b1));
}
__device__ __forceinline__ uint32_t pack_h2(float x, float y) {
    __half2 h = __floats2half2_rn(x, y);
    return *(uint32_t*)&h;
}

// ---------------------------------------------------------------------------
// Weight transpose: Wt[n][k] = W[k][n]
// ---------------------------------------------------------------------------
__global__ __launch_bounds__(256) void transpose_w(
    const float* __restrict__ Wq, const float* __restrict__ Wk, const float* __restrict__ Wv)
{
    const float* W = blockIdx.z == 0 ? Wq : blockIdx.z == 1 ? Wk : Wv;
    float* Wt = g_wt + (size_t)blockIdx.z * HID * HID;
    __shared__ float ts[32][33];
    int tx = threadIdx.x, ty = threadIdx.y;
    int x = blockIdx.x * 32 + tx;
    int y0 = blockIdx.y * 32;
    #pragma unroll
    for (int i = 0; i < 4; i++)
        ts[ty + 8 * i][tx] = W[(size_t)(y0 + ty + 8 * i) * HID + x];
    __syncthreads();
    int x2 = blockIdx.y * 32 + tx;
    int y2 = blockIdx.x * 32;
    #pragma unroll
    for (int i = 0; i < 4; i++)
        Wt[(size_t)(y2 + ty + 8 * i) * HID + x2] = ts[tx][ty + 8 * i];
}

// ---------------------------------------------------------------------------
// FP16 m16n8k16 QKV GEMM (R14-proven): CTA 128x128, 8 warps (2m x 4n), KB=64.
// ---------------------------------------------------------------------------
#define KB 64
#define SAS 36   // b32 words per smem row

__global__ __launch_bounds__(256) void qkv_gemm_mma(
    const float* __restrict__ A,
    const float* __restrict__ bq, const float* __restrict__ bk, const float* __restrict__ bv)
{
    __shared__ uint32_t As[128 * SAS];
    __shared__ uint32_t Bs[128 * SAS];

    const int tid = threadIdx.x;
    const int wid = tid >> 5;
    const int lane = tid & 31;
    const int g = lane >> 2;
    const int tig = lane & 3;
    const int wm = wid & 1;
    const int wn = wid >> 1;

    const int z = blockIdx.z;
    const float* bias = z == 0 ? bq : z == 1 ? bk : bv;
    float* out = z == 0 ? g_q : z == 1 ? g_k : g_v;
    const float* Wt = g_wt + (size_t)z * HID * HID;
    const int m0 = blockIdx.x * 128;
    const int n0 = blockIdx.y * 128;

    float c[4][4][4];
    #pragma unroll
    for (int mt = 0; mt < 4; mt++)
        #pragma unroll
        for (int nt = 0; nt < 4; nt++)
            #pragma unroll
            for (int q = 0; q < 4; q++) c[mt][nt][q] = 0.f;

    for (int k0 = 0; k0 < HID; k0 += KB) {
        __syncthreads();
        #pragma unroll
        for (int it = 0; it < 8; it++) {
            int i = tid + it * 256;
            int row = i >> 4;
            int ch = (i & 15) * 4;
            float4 av = *(const float4*)(A  + (size_t)(m0 + row) * HID + k0 + ch);
            float4 bv4 = *(const float4*)(Wt + (size_t)(n0 + row) * HID + k0 + ch);
            uint2 ap = make_uint2(pack_h2(av.x, av.y), pack_h2(av.z, av.w));
            uint2 bp = make_uint2(pack_h2(bv4.x, bv4.y), pack_h2(bv4.z, bv4.w));
            *(uint2*)(As + row * SAS + (ch >> 1)) = ap;
            *(uint2*)(Bs + row * SAS + (ch >> 1)) = bp;
        }
        __syncthreads();

        #pragma unroll
        for (int ks = 0; ks < 4; ks++) {
            const int kb = ks * 8;
            uint32_t bf[4][2];
            #pragma unroll
            for (int nt = 0; nt < 4; nt++) {
                const uint32_t* bp = Bs + (wn * 32 + nt * 8 + g) * SAS + kb + tig;
                bf[nt][0] = bp[0];
                bf[nt][1] = bp[4];
            }
            #pragma unroll
            for (int mt = 0; mt < 4; mt++) {
                const uint32_t* ap0 = As + (wm * 64 + mt * 16 + g) * SAS + kb + tig;
                const uint32_t* ap1 = ap0 + 8 * SAS;
                uint32_t a0 = ap0[0];
                uint32_t a1 = ap1[0];
                uint32_t a2 = ap0[4];
                uint32_t a3 = ap1[4];
                #pragma unroll
                for (int nt = 0; nt < 4; nt++)
                    mma_f16(c[mt][nt], a0, a1, a2, a3, bf[nt][0], bf[nt][1]);
            }
        }
    }

    #pragma unroll
    for (int mt = 0; mt < 4; mt++) {
        int r0 = m0 + wm * 64 + mt * 16 + g;
        #pragma unroll
        for (int half = 0; half < 2; half++) {
            int r = r0 + half * 8;
            int b = r >> 5;
            int l = r & 31;
            float* obase = out + (((size_t)b * NH) * LQ + l) * HD;
            #pragma unroll
            for (int nt = 0; nt < 4; nt++) {
                int n = n0 + wn * 32 + nt * 8 + tig * 2;
                int h = n >> 6;
                int d = n & 63;
                float2 v;
                v.x = c[mt][nt][half * 2 + 0] + bias[n];
                v.y = c[mt][nt][half * 2 + 1] + bias[n + 1];
                *(float2*)(obase + (size_t)h * LQ * HD + d) = v;
            }
        }
    }
}

// ---------------------------------------------------------------------------
// Batch-paired attention: one CTA per (pair p, head h) handles batches
// b0 = p and b1 = p + 120 (same b%8 -> shared cache0 tiles).
// 64 queries, 4 warps; warp w owns q-rows [w*16, w*16+16).
// 13 iterations: 8 shared cache0 (kv 64), 4 cache1 (kv 32 per batch,
// packed side by side), 1 self (kv 32 per batch).
// Register-only softmax (quad shfl), all-fp16 MMAs, 3 barriers/iter.
// ---------------------------------------------------------------------------
#define SDW 36   // packed word stride (K hi/lo, P)
#define SDV 68   // V fp32 stride

__global__ __launch_bounds__(128) void attn_mma(
    const float* __restrict__ c0k, const float* __restrict__ c0v,
    const float* __restrict__ c1k, const float* __restrict__ c1v,
    const float* __restrict__ mask, float* __restrict__ out)
{
    extern __shared__ float smf[];
    uint32_t* khi_s  = (uint32_t*)smf;            // [64*36]
    uint32_t* klo_s  = khi_s + 64 * SDW;          // [64*36]
    float*    v_s    = (float*)(klo_s + 64 * SDW);// [64*68]
    uint32_t* p_s    = (uint32_t*)(v_s + 64 * SDV); // [64*36]
    float*    mask_s = (float*)(p_s + 64 * SDW);  // [2*676]
    float*    alpha_s = mask_s + 2 * 676;         // [64]
    float*    l_s     = alpha_s + 64;             // [64]

    const int pidx = blockIdx.x / NH;
    const int h = blockIdx.x % NH;
    const int b0 = pidx;
    const int b1 = pidx + NPAIR;
    const int r8 = pidx & 7;       // shared cache0 batch

    const int tid = threadIdx.x;
    const int wid = tid >> 5;
    const int lane = tid & 31;
    const int g = lane >> 2;
    const int tig = lane & 3;
    const int wb = wid >> 1;       // warp's batch (0 or 1)

    // ---- stage Q (both batches) into v_s, scaled; extract A-frags ----
    {
        #pragma unroll
        for (int it = 0; it < 8; it++) {
            int i = tid + it * 128;
            int row = i >> 4;             // 0..63
            int c4 = (i & 15) * 4;
            const float* qp = (row < 32)
                ? g_q + (((size_t)b0 * NH + h) * LQ + row) * HD + c4
                : g_q + (((size_t)b1 * NH + h) * LQ + (row - 32)) * HD + c4;
            float4 v = *(const float4*)qp;
            v.x *= 0.125f; v.y *= 0.125f; v.z *= 0.125f; v.w *= 0.125f;
            *(float4*)(v_s + row * SDV + c4) = v;
        }
    }
    for (int i = tid; i < TOTKV; i += 128) {
        mask_s[i] = mask[(size_t)b0 * TOTKV + i];
        mask_s[676 + i] = mask[(size_t)b1 * TOTKV + i];
    }
    __syncthreads();

    uint32_t aq[4][4];
    {
        int qrow = wid * 16 + g;
        #pragma unroll
        for (int kc = 0; kc < 4; kc++) {
            const float* r0 = v_s + qrow * SDV + kc * 16 + 2 * tig;
            const float* r1 = r0 + 8 * SDV;
            aq[kc][0] = pack_h2(r0[0], r0[1]);
            aq[kc][1] = pack_h2(r1[0], r1[1]);
            aq[kc][2] = pack_h2(r0[8], r0[9]);
            aq[kc][3] = pack_h2(r1[8], r1[9]);
        }
    }

    float o[8][4];
    #pragma unroll
    for (int nt = 0; nt < 8; nt++)
        #pragma unroll
        for (int q = 0; q < 4; q++) o[nt][q] = 0.f;

    float m_r[2] = {-1e30f, -1e30f};
    float l_r[2] = {0.f, 0.f};

    const float* moff = mask_s + wb * 676;

    for (int t = 0; t < 13; ++t) {
        const bool shr = (t < 8);
        const float *kp0, *kp1, *vp0, *vp1;
        int kvbase;
        if (t < 8) {
            size_t off = (((size_t)r8 * NH + h) * LEN0 + t * 64) * HD;
            kp0 = c0k + off; kp1 = kp0 + 32 * HD;
            vp0 = c0v + off; vp1 = vp0 + 32 * HD;
            kvbase = t * 64;
        } else if (t < 12) {
            int j = t - 8;
            size_t o0 = (((size_t)b0 * NH + h) * LEN1 + j * 32) * HD;
            size_t o1 = (((size_t)b1 * NH + h) * LEN1 + j * 32) * HD;
            kp0 = c1k + o0; kp1 = c1k + o1;
            vp0 = c1v + o0; vp1 = c1v + o1;
            kvbase = LEN0 + j * 32;
        } else {
            size_t o0 = ((size_t)b0 * NH + h) * (LQ * HD);
            size_t o1 = ((size_t)b1 * NH + h) * (LQ * HD);
            kp0 = g_k + o0; kp1 = g_k + o1;
            vp0 = g_v + o0; vp1 = g_v + o1;
            kvbase = LEN0 + LEN1;
        }

        __syncthreads();   // bar1: prior PV reads done
        #pragma unroll
        for (int it = 0; it < 8; it++) {
            int i = tid + it * 128;
            int row = i >> 4;
            int c4 = (i & 15) * 4;
            const float* ks = (row < 32) ? kp0 + row * HD + c4 : kp1 + (row - 32) * HD + c4;
            const float* vs = (row < 32) ? vp0 + row * HD + c4 : vp1 + (row - 32) * HD + c4;
            float4 kf = *(const float4*)ks;
            *(float4*)(v_s + row * SDV + c4) = *(const float4*)vs;
            uint32_t h0 = pack_h2(kf.x, kf.y);
            uint32_t h1 = pack_h2(kf.z, kf.w);
            float2 f0 = __half22float2(*(__half2*)&h0);
            float2 f1 = __half22float2(*(__half2*)&h1);
            uint32_t l0 = pack_h2(kf.x - f0.x, kf.y - f0.y);
            uint32_t l1 = pack_h2(kf.z - f1.x, kf.w - f1.y);
            *(uint2*)(khi_s + row * SDW + (c4 >> 1)) = make_uint2(h0, h1);
            *(uint2*)(klo_s + row * SDW + (c4 >> 1)) = make_uint2(l0, l1);
        }
        __syncthreads();   // bar2: tile visible

        const int nthi = shr ? 8 : 4;
        const int roff = shr ? 0 : wb * 32;

        // ---- QK: warp's 16 q x its kv range ----
        float s[8][4];
        #pragma unroll
        for (int nt = 0; nt < 8; nt++)
            #pragma unroll
            for (int q = 0; q < 4; q++) s[nt][q] = 0.f;

        #pragma unroll
        for (int kc = 0; kc < 4; kc++) {
            const uint32_t* a = aq[kc];
            #pragma unroll
            for (int nt = 0; nt < 8; nt++) {
                if (nt < nthi) {
                    int kvrow = roff + nt * 8 + g;
                    const uint32_t* hp = khi_s + kvrow * SDW + kc * 8 + tig;
                    const uint32_t* lp = klo_s + kvrow * SDW + kc * 8 + tig;
                    mma_f16(s[nt], a[0], a[1], a[2], a[3], hp[0], hp[4]);
                    mma_f16(s[nt], a[0], a[1], a[2], a[3], lp[0], lp[4]);
                }
            }
        }

        // ---- register softmax (rows g, g+8 of warp tile) ----
        {
            float mx0 = -1e30f, mx1 = -1e30f;
            #pragma unroll
            for (int nt = 0; nt < 8; nt++) {
                if (nt < nthi) {
                    int mc = kvbase + nt * 8 + 2 * tig;
                    float m0 = moff[mc], m1 = moff[mc + 1];
                    s[nt][0] += m0; s[nt][1] += m1;
                    s[nt][2] += m0; s[nt][3] += m1;
                    mx0 = fmaxf(mx0, fmaxf(s[nt][0], s[nt][1]));
                    mx1 = fmaxf(mx1, fmaxf(s[nt][2], s[nt][3]));
                }
            }
            mx0 = fmaxf(mx0, __shfl_xor_sync(0xffffffffu, mx0, 1));
            mx0 = fmaxf(mx0, __shfl_xor_sync(0xffffffffu, mx0, 2));
            mx1 = fmaxf(mx1, __shfl_xor_sync(0xffffffffu, mx1, 1));
            mx1 = fmaxf(mx1, __shfl_xor_sync(0xffffffffu, mx1, 2));
            float mn0 = fmaxf(m_r[0], mx0);
            float mn1 = fmaxf(m_r[1], mx1);
            float al0 = __expf(m_r[0] - mn0);
            float al1 = __expf(m_r[1] - mn1);

            int q0 = wid * 16 + g;
            float ps0 = 0.f, ps1 = 0.f;
            #pragma unroll
            for (int nt = 0; nt < 8; nt++) {
                if (nt < nthi) {
                    float e0 = __expf(s[nt][0] - mn0);
                    float e1 = __expf(s[nt][1] - mn0);
                    float e2 = __expf(s[nt][2] - mn1);
                    float e3 = __expf(s[nt][3] - mn1);
                    uint32_t pk0 = pack_h2(e0, e1);
                    uint32_t pk1 = pack_h2(e2, e3);
                    p_s[q0 * SDW + nt * 4 + tig] = pk0;
                    p_s[(q0 + 8) * SDW + nt * 4 + tig] = pk1;
                    float2 f0 = __half22float2(*(__half2*)&pk0);
                    float2 f1 = __half22float2(*(__half2*)&pk1);
                    ps0 += f0.x + f0.y;
                    ps1 += f1.x + f1.y;
                }
            }
            ps0 += __shfl_xor_sync(0xffffffffu, ps0, 1);
            ps0 += __shfl_xor_sync(0xffffffffu, ps0, 2);
            ps1 += __shfl_xor_sync(0xffffffffu, ps1, 1);
            ps1 += __shfl_xor_sync(0xffffffffu, ps1, 2);
            l_r[0] = l_r[0] * al0 + ps0;
            l_r[1] = l_r[1] * al1 + ps1;
            m_r[0] = mn0;
            m_r[1] = mn1;
            if (tig == 0) {
                alpha_s[q0] = al0;
                alpha_s[q0 + 8] = al1;
            }
        }
        __syncthreads();   // bar3: P + alpha visible

        // ---- PV: O^T[d][q] += V^T . P^T ----
        #pragma unroll
        for (int nt = 0; nt < 8; nt++) {
            float la0 = alpha_s[nt * 8 + 2 * tig];
            float la1 = alpha_s[nt * 8 + 2 * tig + 1];
            o[nt][0] *= la0; o[nt][1] *= la1;
            o[nt][2] *= la0; o[nt][3] *= la1;
        }
        const int kchi = shr ? 4 : 2;
        const int d = wid * 16 + g;
        #pragma unroll
        for (int kc = 0; kc < 4; kc++) {
            if (kc < kchi) {
                int kvb = kc * 16 + 2 * tig;
                const float* vb0 = v_s + kvb * SDV + d;
                uint32_t a0 = pack_h2(vb0[0],        vb0[SDV]);
                uint32_t a1 = pack_h2(vb0[8],        vb0[SDV + 8]);
                uint32_t a2 = pack_h2(vb0[8 * SDV],  vb0[9 * SDV]);
                uint32_t a3 = pack_h2(vb0[8 * SDV + 8], vb0[9 * SDV + 8]);
                uint32_t b0f = a0, b1f = a1, b2f = a2, b3f = a3;
                if (!shr) {
                    const float* vb1 = v_s + (32 + kvb) * SDV + d;
                    b0f = pack_h2(vb1[0],        vb1[SDV]);
                    b1f = pack_h2(vb1[8],        vb1[SDV + 8]);
                    b2f = pack_h2(vb1[8 * SDV],  vb1[9 * SDV]);
                    b3f = pack_h2(vb1[8 * SDV + 8], vb1[9 * SDV + 8]);
                }
                #pragma unroll
                for (int nt = 0; nt < 8; nt++) {
                    const uint32_t* pb = p_s + (nt * 8 + g) * SDW + kc * 8 + tig;
                    if (nt < 4)
                        mma_f16(o[nt], a0, a1, a2, a3, pb[0], pb[4]);
                    else
                        mma_f16(o[nt], b0f, b1f, b2f, b3f, pb[0], pb[4]);
                }
            }
        }
    }

    // ---- finalize ----
    {
        int q0 = wid * 16 + g;
        if (tig == 0) {
            l_s[q0] = l_r[0];
            l_s[q0 + 8] = l_r[1];
        }
    }
    __syncthreads();

    // normalize and stage O^T (fp32, stride 65) over khi/klo region
    float* ot_s = (float*)khi_s;
    {
        const int d = wid * 16 + g;
        #pragma unroll
        for (int nt = 0; nt < 8; nt++) {
            int q0 = nt * 8 + 2 * tig;
            float il0 = 1.f / l_s[q0];
            float il1 = 1.f / l_s[q0 + 1];
            ot_s[d * 65 + q0]     = o[nt][0] * il0;
            ot_s[d * 65 + q0 + 1] = o[nt][1] * il1;
            ot_s[(d + 8) * 65 + q0]     = o[nt][2] * il0;
            ot_s[(d + 8) * 65 + q0 + 1] = o[nt][3] * il1;
        }
    }
    __syncthreads();

    // coalesced output: thread (q = tid>>1, dseg = tid&1 -> 32 d each)
    {
        int q = tid >> 1;
        int dseg = (tid & 1) * 32;
        int b = (q < 32) ? b0 : b1;
        int row = q & 31;
        float* op = out + ((size_t)(b * LQ + row)) * HID + h * HD + dseg;
        #pragma unroll
        for (int j = 0; j < 8; j++) {
            float4 vv;
            vv.x = ot_s[(dseg + 4 * j + 0) * 65 + q];
            vv.y = ot_s[(dseg + 4 * j + 1) * 65 + q];
            vv.z = ot_s[(dseg + 4 * j + 2) * 65 + q];
            vv.w = ot_s[(dseg + 4 * j + 3) * 65 + q];
            *(float4*)(op + 4 * j) = vv;
        }
    }
}

extern "C" void kernel_launch(void* const* d_in, const int* in_sizes, int n_in,
                              void* d_out, int out_size)
{
    const float* hs   = (const float*)d_in[0];
    const float* mask = (const float*)d_in[1];
    const float* c0k  = (const float*)d_in[2];
    const float* c0v  = (const float*)d_in[3];
    const float* c1k  = (const float*)d_in[4];
    const float* c1v  = (const float*)d_in[5];
    const float* Wq   = (const float*)d_in[6];
    const float* bq   = (const float*)d_in[7];
    const float* Wk   = (const float*)d_in[8];
    const float* bk   = (const float*)d_in[9];
    const float* Wv   = (const float*)d_in[10];
    const float* bv   = (const float*)d_in[11];
    float* out = (float*)d_out;

    // attn dynamic smem: khi+klo (2*9216) + v (17408) + p (9216) + mask (5408) + 512
    const int attn_smem = (64*SDW*4)*2 + 64*SDV*4 + 64*SDW*4 + 2*676*4 + 128*4;
    cudaFuncSetAttribute(attn_mma, cudaFuncAttributeMaxDynamicSharedMemorySize, attn_smem);

    dim3 tgrid(HID / 32, HID / 32, 3);
    transpose_w<<<tgrid, dim3(32, 8)>>>(Wq, Wk, Wv);

    dim3 ggrid(MROWS / 128, HID / 128, 3);
    qkv_gemm_mma<<<ggrid, 256>>>(hs, bq, bk, bv);

    attn_mma<<<NPAIR * NH, 128, attn_smem>>>(c0k, c0v, c1k, c1v, mask, out);
}